// round 11
// baseline (speedup 1.0000x reference)
#include <cuda_runtime.h>

// FasterTensorProduct — bilinear factorization, two kernels.
// out[b,n1,n2,k] = sum_c sh[b,n1,c] * Y[b,n2][k][c],  Y = x @ A_c (weight-derived).

#define IN_DIM 272
#define NROW   512   // B*N
#define NB     4
#define NN     128

#define W0E_OFF 0      // 96 x 64
#define W1O_OFF 6144   // 128 x 32
#define W1E_OFF 10240  // 80 x 32
#define W0O_OFF 12800  // 48 x 16

// Y scratch: [row][k] float4 (c innermost). 512*272*16B = 2.23 MB (L2-resident).
__device__ float4 g_Y[NROW * IN_DIM];

// ---------------------------------------------------------------------------
// Stage 1: R=4 rows per block, 576 threads = 4 quarters x 144 channel-threads.
// Each quarter reduces 1/4 of the contraction range for all 4 rows (weights
// loaded once, FMA'd into 4 row accumulators). Quarters 1-3 write partials to
// smem; ONE uniform __syncthreads(); quarter 0 combines from registers+smem.
// Weight L2 traffic: 128 blocks * 54KB = 6.9 MB (was 27 MB).
// ---------------------------------------------------------------------------
#define RR 4
// Partial layout (floats), quarters 1..3 only, [qq-1][r][chan][comp]:
#define PA 0                      // 3*4*64*4 = 3072
#define PB 3072                   // 3*4*32*7 = 2688
#define PC 5760                   // 3*4*32*7 = 2688
#define PD 8448                   // 3*4*16*4 = 768
#define PTOT 9216                 // 36 KB

__global__ __launch_bounds__(576) void tp_stage1(const float* __restrict__ in_,
                                                 const float* __restrict__ w)
{
    __shared__ float sx[RR][IN_DIM];
    __shared__ float part[PTOT];
    const int r0 = blockIdx.x * RR;
    const int t  = threadIdx.x;

    for (int idx = t; idx < RR * IN_DIM; idx += 576)
        sx[idx / IN_DIM][idx % IN_DIM] = in_[r0 * IN_DIM + idx];
    __syncthreads();

    const int q = t / 144;      // quarter 0..3
    const int u = t - q * 144;  // 0..143

    // acc[r][0..6]: generic per-row partials (layout depends on segment).
    float acc[RR][7] = {};

    // ================= phase A: branchy compute, NO barriers =================
    if (u < 64) {
        // segment A: acc = {a0, a1x, a1y, a1z}
        const int o = u;
        const int j0 = q * 16, k0 = q * 8;
        #pragma unroll
        for (int j = j0; j < j0 + 16; j++) {
            const float wv = w[W0E_OFF + j * 64 + o];
            #pragma unroll
            for (int r = 0; r < RR; r++) acc[r][0] += sx[r][j] * wv;
        }
        #pragma unroll
        for (int k = k0; k < k0 + 8; k++) {
            const float wv = w[W0E_OFF + (64 + k) * 64 + o];
            #pragma unroll
            for (int r = 0; r < RR; r++)
                #pragma unroll
                for (int d = 0; d < 3; d++) acc[r][1 + d] += sx[r][64 + 3 * k + d] * wv;
        }
    }
    else if (u < 96) {
        // segment B: acc = {b0, b1x,b1y,b1z, b2x,b2y,b2z}
        const int o = u - 64;
        const int j0 = q * 16, k0 = q * 8;
        #pragma unroll
        for (int j = j0; j < j0 + 16; j++) {
            const float wv = w[W1O_OFF + j * 32 + o];
            #pragma unroll
            for (int r = 0; r < RR; r++) acc[r][0] += sx[r][j] * wv;
        }
        #pragma unroll
        for (int k = k0; k < k0 + 8; k++) {
            const float wv = w[W1O_OFF + (64 + k) * 32 + o];
            #pragma unroll
            for (int r = 0; r < RR; r++)
                #pragma unroll
                for (int d = 0; d < 3; d++) acc[r][1 + d] += sx[r][64 + 3 * k + d] * wv;
        }
        #pragma unroll
        for (int k = k0; k < k0 + 8; k++) {
            const float wv = w[W1O_OFF + (96 + k) * 32 + o];
            #pragma unroll
            for (int r = 0; r < RR; r++)
                #pragma unroll
                for (int e = 0; e < 3; e++) acc[r][4 + e] += sx[r][160 + 3 * k + e] * wv;
        }
    }
    else if (u < 128) {
        // segment C: acc = {c2, c0x,c0y,c0z, c1x,c1y,c1z}
        const int o = u - 96;
        const int k0 = q * 8, j0 = q * 4;
        #pragma unroll
        for (int k = k0; k < k0 + 8; k++) {
            const float wv = w[W1E_OFF + k * 32 + o];
            #pragma unroll
            for (int r = 0; r < RR; r++)
                #pragma unroll
                for (int e = 0; e < 3; e++) acc[r][1 + e] += sx[r][64 + 3 * k + e] * wv;
        }
        #pragma unroll
        for (int k = k0; k < k0 + 8; k++) {
            const float wv = w[W1E_OFF + (32 + k) * 32 + o];
            #pragma unroll
            for (int r = 0; r < RR; r++)
                #pragma unroll
                for (int d = 0; d < 3; d++) acc[r][4 + d] += sx[r][160 + 3 * k + d] * wv;
        }
        #pragma unroll
        for (int j = j0; j < j0 + 4; j++) {
            const float wv = w[W1E_OFF + (64 + j) * 32 + o];
            #pragma unroll
            for (int r = 0; r < RR; r++) acc[r][0] += sx[r][256 + j] * wv;
        }
    }
    else {
        // segment D: acc = {d1, d0x, d0y, d0z}
        const int o = u - 128;
        const int k0 = q * 8, j0 = q * 4;
        #pragma unroll
        for (int k = k0; k < k0 + 8; k++) {
            const float wv = w[W0O_OFF + k * 16 + o];
            #pragma unroll
            for (int r = 0; r < RR; r++)
                #pragma unroll
                for (int d = 0; d < 3; d++) acc[r][1 + d] += sx[r][160 + 3 * k + d] * wv;
        }
        #pragma unroll
        for (int j = j0; j < j0 + 4; j++) {
            const float wv = w[W0O_OFF + (32 + j) * 16 + o];
            #pragma unroll
            for (int r = 0; r < RR; r++) acc[r][0] += sx[r][256 + j] * wv;
        }
    }

    // ============ phase B: quarters 1-3 publish partials (no barrier) ========
    if (q) {
        const int qq = q - 1;
        if (u < 64) {
            const int o = u;
            #pragma unroll
            for (int r = 0; r < RR; r++) {
                float* p = &part[PA + ((qq * RR + r) * 64 + o) * 4];
                #pragma unroll
                for (int d = 0; d < 4; d++) p[d] = acc[r][d];
            }
        } else if (u < 96) {
            const int o = u - 64;
            #pragma unroll
            for (int r = 0; r < RR; r++) {
                float* p = &part[PB + ((qq * RR + r) * 32 + o) * 7];
                #pragma unroll
                for (int d = 0; d < 7; d++) p[d] = acc[r][d];
            }
        } else if (u < 128) {
            const int o = u - 96;
            #pragma unroll
            for (int r = 0; r < RR; r++) {
                float* p = &part[PC + ((qq * RR + r) * 32 + o) * 7];
                #pragma unroll
                for (int d = 0; d < 7; d++) p[d] = acc[r][d];
            }
        } else {
            const int o = u - 128;
            #pragma unroll
            for (int r = 0; r < RR; r++) {
                float* p = &part[PD + ((qq * RR + r) * 16 + o) * 4];
                #pragma unroll
                for (int d = 0; d < 4; d++) p[d] = acc[r][d];
            }
        }
    }

    __syncthreads();   // SINGLE uniform barrier for the whole block

    // ============ phase C: quarter 0 combines and writes Y ===================
    if (q == 0) {
        if (u < 64) {
            const int o = u;
            const float s  = 0.10206207262f;   // 1/sqrt(96)
            const float s3 = 0.05892556510f;   // 1/sqrt(96*3)
            #pragma unroll
            for (int r = 0; r < RR; r++) {
                float v[4] = {acc[r][0], acc[r][1], acc[r][2], acc[r][3]};
                #pragma unroll
                for (int qq = 0; qq < 3; qq++) {
                    const float* p = &part[PA + ((qq * RR + r) * 64 + o) * 4];
                    #pragma unroll
                    for (int d = 0; d < 4; d++) v[d] += p[d];
                }
                g_Y[(r0 + r) * IN_DIM + o] = make_float4(s * v[0], s3 * v[1], s3 * v[2], s3 * v[3]);
            }
        }
        else if (u < 96) {
            const int o = u - 64;
            const float s   = 0.08838834765f;  // 1/sqrt(128)
            const float si2 = 0.0625f;         // 1/sqrt(256)
            #pragma unroll
            for (int r = 0; r < RR; r++) {
                float z[7];
                #pragma unroll
                for (int d = 0; d < 7; d++) z[d] = acc[r][d];
                #pragma unroll
                for (int qq = 0; qq < 3; qq++) {
                    const float* p = &part[PB + ((qq * RR + r) * 32 + o) * 7];
                    #pragma unroll
                    for (int d = 0; d < 7; d++) z[d] += p[d];
                }
                // z = {b0, b1[3], b2[3]}
                #pragma unroll
                for (int c = 0; c < 3; c++) {
                    float v[4];
                    v[0]               =  s   * z[1 + c];
                    v[1 + c]           =  s   * z[0];
                    v[1 + (c + 2) % 3] =  si2 * z[4 + (c + 1) % 3];
                    v[1 + (c + 1) % 3] = -si2 * z[4 + (c + 2) % 3];
                    g_Y[(r0 + r) * IN_DIM + 64 + 3 * o + c] = make_float4(v[0], v[1], v[2], v[3]);
                }
            }
        }
        else if (u < 128) {
            const int o = u - 96;
            const float s   = 0.11180339887f;  // 1/sqrt(80)
            const float si2 = 0.07905694150f;  // 1/sqrt(160)
            #pragma unroll
            for (int r = 0; r < RR; r++) {
                float z[7];
                #pragma unroll
                for (int d = 0; d < 7; d++) z[d] = acc[r][d];
                #pragma unroll
                for (int qq = 0; qq < 3; qq++) {
                    const float* p = &part[PC + ((qq * RR + r) * 32 + o) * 7];
                    #pragma unroll
                    for (int d = 0; d < 7; d++) z[d] += p[d];
                }
                // z = {c2, c0[3], c1[3]}
                #pragma unroll
                for (int c = 0; c < 3; c++) {
                    float v[4];
                    v[0]               =  s   * z[4 + c];
                    v[1 + c]           =  s   * z[0];
                    v[1 + (c + 2) % 3] =  si2 * z[1 + (c + 1) % 3];
                    v[1 + (c + 1) % 3] = -si2 * z[1 + (c + 2) % 3];
                    g_Y[(r0 + r) * IN_DIM + 160 + 3 * o + c] = make_float4(v[0], v[1], v[2], v[3]);
                }
            }
        }
        else {
            const int o = u - 128;
            const float s  = 0.14433756730f;   // 1/sqrt(48)
            const float s3 = 0.08333333333f;   // 1/12
            #pragma unroll
            for (int r = 0; r < RR; r++) {
                float v[4] = {acc[r][0], acc[r][1], acc[r][2], acc[r][3]};
                #pragma unroll
                for (int qq = 0; qq < 3; qq++) {
                    const float* p = &part[PD + ((qq * RR + r) * 16 + o) * 4];
                    #pragma unroll
                    for (int d = 0; d < 4; d++) v[d] += p[d];
                }
                g_Y[(r0 + r) * IN_DIM + 256 + o] = make_float4(s * v[0], s3 * v[1], s3 * v[2], s3 * v[3]);
            }
        }
    }
}

// ---------------------------------------------------------------------------
// Stage 2 (unchanged, proven 14.4 us):
// out[b,n1,n2,k] = dot4(sh[b,n1], Y[b,n2][k]).
// 256-thread blocks, flat j = n2*68+kv addressing, sh tile in smem,
// 8 n1 per thread fully unrolled. Grid (34, 16, 4).
// ---------------------------------------------------------------------------
#define T1 8

__global__ __launch_bounds__(256, 6) void tp_stage2(const float* __restrict__ sh,
                                                    float* __restrict__ out)
{
    __shared__ float4 ssh[T1];
    const int tid = threadIdx.x;
    const int b   = blockIdx.z;
    const int n1b = blockIdx.y * T1;
    const int j   = blockIdx.x * 256 + tid;   // n2*68 + kv, 0..8703

    if (tid < T1)
        ssh[tid] = reinterpret_cast<const float4*>(sh)[b * NN + n1b + tid];
    __syncthreads();

    const int n2 = j / 68;
    const int kv = j - n2 * 68;

    const float4* Yp = &g_Y[(b * NN + n2) * IN_DIM + kv * 4];
    const float4 y0 = Yp[0], y1 = Yp[1], y2 = Yp[2], y3 = Yp[3];

    float4* op = reinterpret_cast<float4*>(out)
               + (size_t)(b * NN + n1b) * (NN * (IN_DIM / 4)) + j;
    const size_t stride = NN * (IN_DIM / 4);  // 8704 float4 per n1

    #pragma unroll
    for (int i = 0; i < T1; i++) {
        const float4 s = ssh[i];
        float4 o;
        o.x = s.x * y0.x + s.y * y0.y + s.z * y0.z + s.w * y0.w;
        o.y = s.x * y1.x + s.y * y1.y + s.z * y1.z + s.w * y1.w;
        o.z = s.x * y2.x + s.y * y2.y + s.z * y2.z + s.w * y2.w;
        o.w = s.x * y3.x + s.y * y3.y + s.z * y3.z + s.w * y3.w;
        op[i * stride] = o;
    }
}

extern "C" void kernel_launch(void* const* d_in, const int* in_sizes, int n_in,
                              void* d_out, int out_size)
{
    const float* in_ = (const float*)d_in[0];   // (4,1,128,272)
    const float* sh  = (const float*)d_in[1];   // (4,128,1,4)
    const float* w   = (const float*)d_in[2];   // (13568,)
    float* out = (float*)d_out;

    tp_stage1<<<NROW / RR, 576>>>(in_, w);
    tp_stage2<<<dim3(34, NN / T1, NB), 256>>>(sh, out);
}